// round 8
// baseline (speedup 1.0000x reference)
#include <cuda_runtime.h>
#include <math.h>
#include <stdint.h>

#define BB 4
#define SS 4096
#define DD 256
#define HH 4
#define HD 64
#define NN (BB*SS)
#define INV_TEMP 0.125f
#define LN_EPS 1e-5f

typedef unsigned long long ull;

// Scratch (allocation-free): 8 x 16 MiB device globals.
__device__ float g_xn[NN*DD];
__device__ float g_q[NN*DD];
__device__ float g_k[NN*DD];
__device__ float g_v[NN*DD];
__device__ float g_att[NN*DD];
__device__ float g_xt[NN*DD];
__device__ float g_h[NN*DD];
__device__ float g_a1[NN*DD];

// ---- packed f32x2 helpers (Blackwell base-ISA; 2 fp32 per FMA-pipe issue) ----
__device__ __forceinline__ ull ffma2(ull a, ull b, ull c) {
    ull d; asm("fma.rn.f32x2 %0, %1, %2, %3;" : "=l"(d) : "l"(a), "l"(b), "l"(c)); return d;
}
__device__ __forceinline__ ull fmul2(ull a, ull b) {
    ull d; asm("mul.rn.f32x2 %0, %1, %2;" : "=l"(d) : "l"(a), "l"(b)); return d;
}
__device__ __forceinline__ ull pack2(float lo, float hi) {
    ull d; asm("mov.b64 %0, {%1, %2};" : "=l"(d) : "f"(lo), "f"(hi)); return d;
}
__device__ __forceinline__ void unpack2(ull v, float& lo, float& hi) {
    asm("mov.b64 {%0, %1}, %2;" : "=f"(lo), "=f"(hi) : "l"(v));
}
__device__ __forceinline__ float hsum2(ull v) {
    float lo, hi; unpack2(v, lo, hi); return lo + hi;
}

// ---- cp.async (Ampere+ base ISA) ----
__device__ __forceinline__ uint32_t smem_u32(const void* p) {
    uint32_t a;
    asm("{ .reg .u64 t; cvta.to.shared.u64 t, %1; cvt.u32.u64 %0, t; }" : "=r"(a) : "l"(p));
    return a;
}
__device__ __forceinline__ void cp_async16(uint32_t saddr, const void* g) {
    asm volatile("cp.async.cg.shared.global [%0], [%1], 16;" :: "r"(saddr), "l"(g));
}
#define CP_COMMIT() asm volatile("cp.async.commit_group;" ::: "memory")
#define CP_WAIT0()  asm volatile("cp.async.wait_group 0;" ::: "memory")

__device__ __forceinline__ float warp_sum(float v) {
    #pragma unroll
    for (int o = 16; o; o >>= 1) v += __shfl_xor_sync(0xffffffffu, v, o);
    return v;
}

// LayerNorm (optionally fused residual add). One block per row, 256 threads.
__global__ void ln_kernel(const float* __restrict__ x, const float* __restrict__ res,
                          const float* __restrict__ g, const float* __restrict__ b,
                          float* __restrict__ xt_out, float* __restrict__ y) {
    int row = blockIdx.x;
    int t = threadIdx.x;
    size_t i = (size_t)row * DD + t;
    float v = x[i];
    if (res) v += res[i];
    if (xt_out) xt_out[i] = v;

    __shared__ float red1[8], red2[8];
    float s1 = warp_sum(v);
    float s2 = warp_sum(v * v);
    if ((t & 31) == 0) { red1[t >> 5] = s1; red2[t >> 5] = s2; }
    __syncthreads();
    float tot = 0.f, tot2 = 0.f;
    #pragma unroll
    for (int w = 0; w < 8; w++) { tot += red1[w]; tot2 += red2[w]; }
    float mu = tot * (1.f / DD);
    float var = tot2 * (1.f / DD) - mu * mu;
    float rstd = rsqrtf(var + LN_EPS);
    y[i] = (v - mu) * rstd * g[t] + b[t];
}

// C[M,256] = A[M,256] @ W[256,256]^T  (torch Linear). NT GEMM, FFMA2 k-packed,
// register-prefetch double buffering (LDG for k0+16 issued before compute of k0).
// BM=128, BN=64, BK=16; 256 threads; per-thread 8 rows x 4 interleaved cols.
// epi: 0 = plain store; 1 = +bias, relu; 2 = +bias +res
#define GS 18
__global__ void __launch_bounds__(256, 2) gemm_nt(
        const float* __restrict__ A, const float* __restrict__ W,
        const float* __restrict__ bias, const float* __restrict__ res,
        float* __restrict__ C, int epi) {
    __shared__ float As[128 * GS];
    __shared__ float Bs[64 * GS];
    int tid = threadIdx.x;
    int bm = blockIdx.y * 128, bn = blockIdx.x * 64;
    int tr = (tid >> 4) * 8;      // 0..120
    int tc = tid & 15;            // 0..15

    // load indices (fixed per thread)
    int am0 = tid >> 2,          ak0 = (tid & 3) * 4;          // A row / k-offset, part 0
    int am1 = (tid + 256) >> 2,  ak1 = ((tid + 256) & 3) * 4;  // part 1
    int wn  = tid >> 2,          wk  = (tid & 3) * 4;          // W row / k-offset

    ull acc2[8][4];
    #pragma unroll
    for (int i = 0; i < 8; i++)
        #pragma unroll
        for (int j = 0; j < 4; j++) acc2[i][j] = 0ull;

    float4 pa0 = *(const float4*)&A[(size_t)(bm + am0) * DD + ak0];
    float4 pa1 = *(const float4*)&A[(size_t)(bm + am1) * DD + ak1];
    float4 pb  = *(const float4*)&W[(size_t)(bn + wn)  * DD + wk];

    for (int k0 = 0; k0 < DD; k0 += 16) {
        As[am0 * GS + ak0 + 0] = pa0.x; As[am0 * GS + ak0 + 1] = pa0.y;
        As[am0 * GS + ak0 + 2] = pa0.z; As[am0 * GS + ak0 + 3] = pa0.w;
        As[am1 * GS + ak1 + 0] = pa1.x; As[am1 * GS + ak1 + 1] = pa1.y;
        As[am1 * GS + ak1 + 2] = pa1.z; As[am1 * GS + ak1 + 3] = pa1.w;
        Bs[wn  * GS + wk  + 0] = pb.x;  Bs[wn  * GS + wk  + 1] = pb.y;
        Bs[wn  * GS + wk  + 2] = pb.z;  Bs[wn  * GS + wk  + 3] = pb.w;
        __syncthreads();

        if (k0 + 16 < DD) {  // prefetch next slice while computing this one
            pa0 = *(const float4*)&A[(size_t)(bm + am0) * DD + k0 + 16 + ak0];
            pa1 = *(const float4*)&A[(size_t)(bm + am1) * DD + k0 + 16 + ak1];
            pb  = *(const float4*)&W[(size_t)(bn + wn)  * DD + k0 + 16 + wk];
        }

        #pragma unroll
        for (int kk = 0; kk < 16; kk += 2) {
            ull a2[8], b2[4];
            #pragma unroll
            for (int i = 0; i < 8; i++) a2[i] = *(const ull*)&As[(tr + i) * GS + kk];
            #pragma unroll
            for (int j = 0; j < 4; j++) b2[j] = *(const ull*)&Bs[(tc + 16 * j) * GS + kk];
            #pragma unroll
            for (int i = 0; i < 8; i++)
                #pragma unroll
                for (int j = 0; j < 4; j++) acc2[i][j] = ffma2(a2[i], b2[j], acc2[i][j]);
        }
        __syncthreads();
    }

    #pragma unroll
    for (int i = 0; i < 8; i++) {
        int m = bm + tr + i;
        #pragma unroll
        for (int j = 0; j < 4; j++) {
            int n = bn + tc + 16 * j;
            float v = hsum2(acc2[i][j]);
            if (epi >= 1) v += bias[n];
            if (epi == 1) v = fmaxf(v, 0.f);
            if (epi == 2) v += res[(size_t)m * DD + n];
            C[(size_t)m * DD + n] = v;
        }
    }
}

// Flash attention, causal. One block per (64-row q-tile, b*h). 256 threads.
// Register-blocked 4x4 micro-tile, FFMA2-packed, cp.async double-buffered K/V
// (prefetch tile kt+1 while computing kt; ONE barrier per tile), 2 CTAs/SM.
#define SP 68
#define TILF (64 * SP)                 // floats per 64-row tile
#define SMEM_ATTN (6 * TILF * 4)       // Q | K0 | V0 | K1 | V1 | P = 104448 B
__global__ void __launch_bounds__(256, 2) attn_kernel(
        const float* __restrict__ q, const float* __restrict__ k,
        const float* __restrict__ v, float* __restrict__ att) {
    extern __shared__ float sm[];
    float* Qs = sm;
    float* Ps = sm + 5 * TILF;
    uint32_t sbase = smem_u32(sm);

    int bh = blockIdx.y;
    int b = bh >> 2, h = bh & 3;
    int qt = 63 - blockIdx.x;  // longest blocks launch first
    int tid = threadIdx.x;
    int ty = tid >> 4;
    int tx = tid & 15;

    const float* qbase = q + (size_t)b * SS * DD + h * HD;
    const float* kbase = k + (size_t)b * SS * DD + h * HD;
    const float* vbase = v + (size_t)b * SS * DD + h * HD;

    // per-thread fixed load pattern: 4 chunks of (rr, d4)
    int lrr[4], ld4[4];
    #pragma unroll
    for (int it = 0; it < 4; it++) {
        int l = tid + it * 256;
        lrr[it] = l >> 4;
        ld4[it] = (l & 15) * 4;
    }

    // Load Q tile (scaled); issue cp.async for K/V tile 0 into buffer 0.
    #pragma unroll
    for (int it = 0; it < 4; it++) {
        float4 tv = *(const float4*)&qbase[(size_t)(qt * 64 + lrr[it]) * DD + ld4[it]];
        Qs[lrr[it] * SP + ld4[it] + 0] = tv.x * INV_TEMP;
        Qs[lrr[it] * SP + ld4[it] + 1] = tv.y * INV_TEMP;
        Qs[lrr[it] * SP + ld4[it] + 2] = tv.z * INV_TEMP;
        Qs[lrr[it] * SP + ld4[it] + 3] = tv.w * INV_TEMP;
    }
    #pragma unroll
    for (int it = 0; it < 4; it++) {
        size_t gofs = ((size_t)lrr[it] * DD + ld4[it]) * 4;
        uint32_t sofs = (uint32_t)(lrr[it] * SP + ld4[it]) * 4;
        cp_async16(sbase + (1 * TILF) * 4 + sofs, (const char*)kbase + gofs);
        cp_async16(sbase + (2 * TILF) * 4 + sofs, (const char*)vbase + gofs);
    }
    CP_COMMIT();

    ull acc2[4][2];
    float m_i[4], l_i[4];
    #pragma unroll
    for (int rr = 0; rr < 4; rr++) {
        m_i[rr] = -INFINITY; l_i[rr] = 0.f;
        acc2[rr][0] = 0ull; acc2[rr][1] = 0ull;
    }

    for (int kt = 0; kt <= qt; kt++) {
        int buf = kt & 1;
        CP_WAIT0();
        __syncthreads();   // tile kt resident; prior tile fully consumed by all warps

        if (kt < qt) {     // prefetch tile kt+1 into the other buffer
            const float* kb = kbase + (size_t)(kt + 1) * 64 * DD;
            const float* vb = vbase + (size_t)(kt + 1) * 64 * DD;
            uint32_t kofs = (uint32_t)(1 + 2 * (buf ^ 1)) * TILF * 4;
            uint32_t vofs = (uint32_t)(2 + 2 * (buf ^ 1)) * TILF * 4;
            #pragma unroll
            for (int it = 0; it < 4; it++) {
                size_t gofs = ((size_t)lrr[it] * DD + ld4[it]) * 4;
                uint32_t sofs = (uint32_t)(lrr[it] * SP + ld4[it]) * 4;
                cp_async16(sbase + kofs + sofs, (const char*)kb + gofs);
                cp_async16(sbase + vofs + sofs, (const char*)vb + gofs);
            }
            CP_COMMIT();
        }

        const float* Ks = sm + (1 + 2 * buf) * TILF;
        const float* Vs = sm + (2 + 2 * buf) * TILF;

        // Scores packed over d-pairs.
        ull s2[4][4];
        #pragma unroll
        for (int rr = 0; rr < 4; rr++)
            #pragma unroll
            for (int c = 0; c < 4; c++) s2[rr][c] = 0ull;

        #pragma unroll
        for (int d0 = 0; d0 < 64; d0 += 4) {
            ulonglong2 qp[4], kp[4];
            #pragma unroll
            for (int rr = 0; rr < 4; rr++)
                qp[rr] = *(const ulonglong2*)&Qs[(ty * 4 + rr) * SP + d0];
            #pragma unroll
            for (int c = 0; c < 4; c++)
                kp[c] = *(const ulonglong2*)&Ks[(tx + 16 * c) * SP + d0];
            #pragma unroll
            for (int rr = 0; rr < 4; rr++)
                #pragma unroll
                for (int c = 0; c < 4; c++) {
                    s2[rr][c] = ffma2(qp[rr].x, kp[c].x, s2[rr][c]);
                    s2[rr][c] = ffma2(qp[rr].y, kp[c].y, s2[rr][c]);
                }
        }

        float s[4][4];
        #pragma unroll
        for (int rr = 0; rr < 4; rr++)
            #pragma unroll
            for (int c = 0; c < 4; c++) s[rr][c] = hsum2(s2[rr][c]);

        bool diag = (kt == qt);
        #pragma unroll
        for (int rr = 0; rr < 4; rr++) {
            int row = ty * 4 + rr;
            float mx = -INFINITY;
            #pragma unroll
            for (int c = 0; c < 4; c++) {
                int j = tx + 16 * c;
                if (diag && j > row) s[rr][c] = -INFINITY;
                mx = fmaxf(mx, s[rr][c]);
            }
            mx = fmaxf(mx, __shfl_xor_sync(0xffffffffu, mx, 1));
            mx = fmaxf(mx, __shfl_xor_sync(0xffffffffu, mx, 2));
            mx = fmaxf(mx, __shfl_xor_sync(0xffffffffu, mx, 4));
            mx = fmaxf(mx, __shfl_xor_sync(0xffffffffu, mx, 8));
            float m_new = fmaxf(m_i[rr], mx);
            float alpha = __expf(m_i[rr] - m_new);

            float lsum = 0.f;
            #pragma unroll
            for (int c = 0; c < 4; c++) {
                float p = __expf(s[rr][c] - m_new);
                lsum += p;
                Ps[row * SP + tx + 16 * c] = p;
            }
            lsum += __shfl_xor_sync(0xffffffffu, lsum, 1);
            lsum += __shfl_xor_sync(0xffffffffu, lsum, 2);
            lsum += __shfl_xor_sync(0xffffffffu, lsum, 4);
            lsum += __shfl_xor_sync(0xffffffffu, lsum, 8);
            l_i[rr] = l_i[rr] * alpha + lsum;
            m_i[rr] = m_new;
            ull al2 = pack2(alpha, alpha);
            acc2[rr][0] = fmul2(acc2[rr][0], al2);
            acc2[rr][1] = fmul2(acc2[rr][1], al2);
        }

        // P rows for this thread are produced & consumed within the same warp.
        __syncwarp();

        // PV packed over output-col pairs.
        #pragma unroll
        for (int j0 = 0; j0 < 64; j0 += 4) {
            float4 pv[4];
            ulonglong2 vv[4];
            #pragma unroll
            for (int rr = 0; rr < 4; rr++)
                pv[rr] = *(const float4*)&Ps[(ty * 4 + rr) * SP + j0];
            #pragma unroll
            for (int jj = 0; jj < 4; jj++)
                vv[jj] = *(const ulonglong2*)&Vs[(j0 + jj) * SP + tx * 4];
            #pragma unroll
            for (int rr = 0; rr < 4; rr++) {
                const float* pr = &pv[rr].x;
                #pragma unroll
                for (int jj = 0; jj < 4; jj++) {
                    ull pb = pack2(pr[jj], pr[jj]);
                    acc2[rr][0] = ffma2(pb, vv[jj].x, acc2[rr][0]);
                    acc2[rr][1] = ffma2(pb, vv[jj].y, acc2[rr][1]);
                }
            }
        }
        // no trailing barrier: next iteration's CP_WAIT0 + __syncthreads guards reuse
    }

    float* obase = att + (size_t)b * SS * DD + h * HD;
    #pragma unroll
    for (int rr = 0; rr < 4; rr++) {
        float inv = 1.f / l_i[rr];
        size_t orow = (size_t)(qt * 64 + ty * 4 + rr) * DD + tx * 4;
        float a0, a1, a2, a3;
        unpack2(acc2[rr][0], a0, a1);
        unpack2(acc2[rr][1], a2, a3);
        float4 o = make_float4(a0 * inv, a1 * inv, a2 * inv, a3 * inv);
        *(float4*)&obase[orow] = o;
    }
}

extern "C" void kernel_launch(void* const* d_in, const int* in_sizes, int n_in,
                              void* d_out, int out_size) {
    const float* x   = (const float*)d_in[0];
    const float* Wq  = (const float*)d_in[1];
    const float* Wk  = (const float*)d_in[2];
    const float* Wv  = (const float*)d_in[3];
    const float* g1  = (const float*)d_in[4];
    const float* b1  = (const float*)d_in[5];
    const float* g2  = (const float*)d_in[6];
    const float* b2  = (const float*)d_in[7];
    const float* W1  = (const float*)d_in[8];
    const float* bf1 = (const float*)d_in[9];
    const float* W2  = (const float*)d_in[10];
    const float* bf2 = (const float*)d_in[11];
    float* out = (float*)d_out;

    float *xn, *q, *k, *v, *att, *xt, *h, *a1;
    cudaGetSymbolAddress((void**)&xn,  g_xn);
    cudaGetSymbolAddress((void**)&q,   g_q);
    cudaGetSymbolAddress((void**)&k,   g_k);
    cudaGetSymbolAddress((void**)&v,   g_v);
    cudaGetSymbolAddress((void**)&att, g_att);
    cudaGetSymbolAddress((void**)&xt,  g_xt);
    cudaGetSymbolAddress((void**)&h,   g_h);
    cudaGetSymbolAddress((void**)&a1,  g_a1);

    cudaFuncSetAttribute(attn_kernel, cudaFuncAttributeMaxDynamicSharedMemorySize, SMEM_ATTN);

    // 1. xn = LN(x)
    ln_kernel<<<NN, 256>>>(x, nullptr, g1, b1, nullptr, xn);
    // 2. QKV projections
    gemm_nt<<<dim3(DD / 64, NN / 128), 256>>>(xn, Wq, nullptr, nullptr, q, 0);
    gemm_nt<<<dim3(DD / 64, NN / 128), 256>>>(xn, Wk, nullptr, nullptr, k, 0);
    gemm_nt<<<dim3(DD / 64, NN / 128), 256>>>(xn, Wv, nullptr, nullptr, v, 0);
    // 3. causal flash attention
    attn_kernel<<<dim3(SS / 64, BB * HH), 256, SMEM_ATTN>>>(q, k, v, att);
    // 4. xt = x + att; h = LN(xt)
    ln_kernel<<<NN, 256>>>(x, att, g2, b2, xt, h);
    // 5. a1 = relu(h @ W1^T + bf1)
    gemm_nt<<<dim3(DD / 64, NN / 128), 256>>>(h, W1, bf1, nullptr, a1, 1);
    // 6. out = xt + a1 @ W2^T + bf2
    gemm_nt<<<dim3(DD / 64, NN / 128), 256>>>(a1, W2, bf2, xt, out, 2);
}